// round 1
// baseline (speedup 1.0000x reference)
#include <cuda_runtime.h>
#include <math.h>

#define HH 512
#define WW 512
#define KK 8
#define HIDN 128
#define DIMN 32

// ---------------- scratch (static device globals; no runtime allocation) ----
__device__ float g_fm[(size_t)KK * HH * WW * 64];   // [k][y][x][64]: ch0-31=fz, ch32-63=fc
__device__ float g_hid[(size_t)KK * HH * WW * 64];  // reused: sup1 out (32ch layout), mpn1 out (64ch)
__device__ float g_fuse[(size_t)HH * WW * KK];      // [y][x][k]
__device__ float g_un[(size_t)HH * WW * 32];        // [y][x][32]

// ============================================================================
// MLP kernel: per-point 4-layer MLP -> g_fm channels 0..31 (masked)
// 64 points per block, 256 threads.
// Activations in smem As[pt][feat] (64 x 132, padded). Weights via __ldg (L1/L2).
// ============================================================================

__device__ __forceinline__ void gemm_64x128(const float (*As)[132],
                                            const float* __restrict__ Wt,
                                            int tx, int ty, float c[4][8]) {
#pragma unroll
    for (int i = 0; i < 4; i++)
#pragma unroll
        for (int j = 0; j < 8; j++) c[i][j] = 0.0f;

    for (int kk = 0; kk < 128; kk += 4) {
        float4 a[4];
#pragma unroll
        for (int i = 0; i < 4; i++)
            a[i] = *(const float4*)&As[ty * 4 + i][kk];
        float4 b0[4], b1[4];
#pragma unroll
        for (int r = 0; r < 4; r++) {
            const float* wrow = Wt + (size_t)(kk + r) * 128 + tx * 8;
            b0[r] = __ldg((const float4*)wrow);
            b1[r] = __ldg((const float4*)(wrow + 4));
        }
#pragma unroll
        for (int i = 0; i < 4; i++) {
            float av[4] = {a[i].x, a[i].y, a[i].z, a[i].w};
#pragma unroll
            for (int r = 0; r < 4; r++) {
                c[i][0] += av[r] * b0[r].x;
                c[i][1] += av[r] * b0[r].y;
                c[i][2] += av[r] * b0[r].z;
                c[i][3] += av[r] * b0[r].w;
                c[i][4] += av[r] * b1[r].x;
                c[i][5] += av[r] * b1[r].y;
                c[i][6] += av[r] * b1[r].z;
                c[i][7] += av[r] * b1[r].w;
            }
        }
    }
}

__global__ __launch_bounds__(256) void mlp_kernel(
    const float* __restrict__ ray, const float* __restrict__ zbufs,
    const float* __restrict__ W1, const float* __restrict__ b1,
    const float* __restrict__ W2, const float* __restrict__ b2,
    const float* __restrict__ W3, const float* __restrict__ b3,
    const float* __restrict__ W4, const float* __restrict__ b4,
    float* __restrict__ fm) {
    __shared__ __align__(16) float As[64][132];
    __shared__ float s_xyz[3][64];
    __shared__ float s_dirs[3][64];
    __shared__ float s_mask[64];

    const int tid = threadIdx.x;
    const size_t base = (size_t)blockIdx.x * 64;

    if (tid < 64) {
        size_t p = base + tid;
        int k = (int)(p / ((size_t)HH * WW));
        int rem = (int)(p % ((size_t)HH * WW));
        int y = rem / WW, x = rem % WW;
        const float* r = ray + (size_t)(y * WW + x) * 7;
        float z = zbufs[(size_t)(y * WW + x) * KK + k];
        float s = z / r[6];
        s_xyz[0][tid] = r[0] + r[3] * s;
        s_xyz[1][tid] = r[1] + r[4] * s;
        s_xyz[2][tid] = r[2] + r[5] * s;
        s_dirs[0][tid] = r[3];
        s_dirs[1][tid] = r[4];
        s_dirs[2][tid] = r[5];
        s_mask[tid] = (z > 0.0f) ? 1.0f : 0.0f;
    }
    __syncthreads();

    // ---- layer 1: h1 = relu(xyz @ W1 + b1) ----
    {
        int p = tid & 63;
        int jb = (tid >> 6) * 32;
        float x0 = s_xyz[0][p], x1 = s_xyz[1][p], x2 = s_xyz[2][p];
#pragma unroll
        for (int j = 0; j < 32; j++) {
            int jj = jb + j;
            float v = __ldg(&b1[jj]) + x0 * __ldg(&W1[jj]) + x1 * __ldg(&W1[128 + jj]) +
                      x2 * __ldg(&W1[256 + jj]);
            As[p][jj] = fmaxf(v, 0.0f);
        }
    }
    __syncthreads();

    const int tx = tid & 15;
    const int ty = tid >> 4;
    float c[4][8];

    // ---- layer 2: h2 = relu(h1 @ W2 + b2) ----
    gemm_64x128(As, W2, tx, ty, c);
    {
        float4 bb0 = __ldg((const float4*)&b2[tx * 8]);
        float4 bb1 = __ldg((const float4*)&b2[tx * 8 + 4]);
        __syncthreads();
#pragma unroll
        for (int i = 0; i < 4; i++) {
            int p = ty * 4 + i;
            float4 v0, v1;
            v0.x = fmaxf(c[i][0] + bb0.x, 0.0f);
            v0.y = fmaxf(c[i][1] + bb0.y, 0.0f);
            v0.z = fmaxf(c[i][2] + bb0.z, 0.0f);
            v0.w = fmaxf(c[i][3] + bb0.w, 0.0f);
            v1.x = fmaxf(c[i][4] + bb1.x, 0.0f);
            v1.y = fmaxf(c[i][5] + bb1.y, 0.0f);
            v1.z = fmaxf(c[i][6] + bb1.z, 0.0f);
            v1.w = fmaxf(c[i][7] + bb1.w, 0.0f);
            *(float4*)&As[p][tx * 8] = v0;
            *(float4*)&As[p][tx * 8 + 4] = v1;
        }
        __syncthreads();
    }

    // ---- layer 3: h3 = relu([h2, dirs] @ W3 + b3) ----
    gemm_64x128(As, W3, tx, ty, c);
    {
        // dirs tail rows 128..130 of W3
        float4 w30a = __ldg((const float4*)&W3[(size_t)128 * 128 + tx * 8]);
        float4 w30b = __ldg((const float4*)&W3[(size_t)128 * 128 + tx * 8 + 4]);
        float4 w31a = __ldg((const float4*)&W3[(size_t)129 * 128 + tx * 8]);
        float4 w31b = __ldg((const float4*)&W3[(size_t)129 * 128 + tx * 8 + 4]);
        float4 w32a = __ldg((const float4*)&W3[(size_t)130 * 128 + tx * 8]);
        float4 w32b = __ldg((const float4*)&W3[(size_t)130 * 128 + tx * 8 + 4]);
        float4 bb0 = __ldg((const float4*)&b3[tx * 8]);
        float4 bb1 = __ldg((const float4*)&b3[tx * 8 + 4]);
#pragma unroll
        for (int i = 0; i < 4; i++) {
            int p = ty * 4 + i;
            float d0 = s_dirs[0][p], d1 = s_dirs[1][p], d2 = s_dirs[2][p];
            c[i][0] += d0 * w30a.x + d1 * w31a.x + d2 * w32a.x;
            c[i][1] += d0 * w30a.y + d1 * w31a.y + d2 * w32a.y;
            c[i][2] += d0 * w30a.z + d1 * w31a.z + d2 * w32a.z;
            c[i][3] += d0 * w30a.w + d1 * w31a.w + d2 * w32a.w;
            c[i][4] += d0 * w30b.x + d1 * w31b.x + d2 * w32b.x;
            c[i][5] += d0 * w30b.y + d1 * w31b.y + d2 * w32b.y;
            c[i][6] += d0 * w30b.z + d1 * w31b.z + d2 * w32b.z;
            c[i][7] += d0 * w30b.w + d1 * w31b.w + d2 * w32b.w;
        }
        __syncthreads();
#pragma unroll
        for (int i = 0; i < 4; i++) {
            int p = ty * 4 + i;
            float4 v0, v1;
            v0.x = fmaxf(c[i][0] + bb0.x, 0.0f);
            v0.y = fmaxf(c[i][1] + bb0.y, 0.0f);
            v0.z = fmaxf(c[i][2] + bb0.z, 0.0f);
            v0.w = fmaxf(c[i][3] + bb0.w, 0.0f);
            v1.x = fmaxf(c[i][4] + bb1.x, 0.0f);
            v1.y = fmaxf(c[i][5] + bb1.y, 0.0f);
            v1.z = fmaxf(c[i][6] + bb1.z, 0.0f);
            v1.w = fmaxf(c[i][7] + bb1.w, 0.0f);
            *(float4*)&As[p][tx * 8] = v0;
            *(float4*)&As[p][tx * 8 + 4] = v1;
        }
        __syncthreads();
    }

    // ---- layer 4: feat = (h3 @ W4 + b4) * mask -> fm[:, 0:32] ----
    {
        int p = tid & 63;
        int jb = (tid >> 6) * 8;
        float acc[8];
#pragma unroll
        for (int j = 0; j < 8; j++) acc[j] = 0.0f;
        for (int kk = 0; kk < 128; kk += 4) {
            float4 a = *(const float4*)&As[p][kk];
            float av[4] = {a.x, a.y, a.z, a.w};
#pragma unroll
            for (int r = 0; r < 4; r++) {
                const float* wrow = W4 + (size_t)(kk + r) * 32 + jb;
                float4 w0 = __ldg((const float4*)wrow);
                float4 w1 = __ldg((const float4*)(wrow + 4));
                acc[0] += av[r] * w0.x;
                acc[1] += av[r] * w0.y;
                acc[2] += av[r] * w0.z;
                acc[3] += av[r] * w0.w;
                acc[4] += av[r] * w1.x;
                acc[5] += av[r] * w1.y;
                acc[6] += av[r] * w1.z;
                acc[7] += av[r] * w1.w;
            }
        }
        float mk = s_mask[p];
        float4 bb0 = __ldg((const float4*)&b4[jb]);
        float4 bb1 = __ldg((const float4*)&b4[jb + 4]);
        float4 o0, o1;
        o0.x = (acc[0] + bb0.x) * mk;
        o0.y = (acc[1] + bb0.y) * mk;
        o0.z = (acc[2] + bb0.z) * mk;
        o0.w = (acc[3] + bb0.w) * mk;
        o1.x = (acc[4] + bb1.x) * mk;
        o1.y = (acc[5] + bb1.y) * mk;
        o1.z = (acc[6] + bb1.z) * mk;
        o1.w = (acc[7] + bb1.w) * mk;
        float* dst = fm + (base + p) * 64 + jb;
        *(float4*)dst = o0;
        *(float4*)(dst + 4) = o1;
    }
}

// ============================================================================
// Generic direct 3x3 SAME conv, 16x16 output tile, cin-chunked.
// in index = layer*layer_stride + (y*W+x)*pix_stride + layer*chmul + ci
// out index = (layer*H*W + y*W + x)*out_stride + out_off + co
// ============================================================================
template <int CIN, int CCH, int COUT, bool RELU>
__global__ __launch_bounds__(256) void conv3x3_kernel(
    const float* __restrict__ in, const float* __restrict__ w,
    const float* __restrict__ bias, float* __restrict__ out, int pix_stride,
    long long layer_stride, int chmul, int out_stride, int out_off) {
    __shared__ __align__(16) float s_in[CCH][18][18];
    __shared__ __align__(16) float s_w[9][CCH][COUT];

    const int tid = threadIdx.x;
    const int bx = blockIdx.x, by = blockIdx.y, layer = blockIdx.z;
    const int x0 = bx * 16 - 1, y0 = by * 16 - 1;
    const int tx = tid & 15, ty = tid >> 4;

    float acc[COUT];
#pragma unroll
    for (int c = 0; c < COUT; c++) acc[c] = 0.0f;

    const float* inbase = in + (size_t)layer * (size_t)layer_stride + (size_t)layer * chmul;

    for (int cb = 0; cb < CIN; cb += CCH) {
        __syncthreads();
        // load input tile chunk
        for (int idx = tid; idx < 18 * 18; idx += 256) {
            int yy = idx / 18, xx = idx % 18;
            int gy = y0 + yy, gx = x0 + xx;
            if (gy >= 0 && gy < HH && gx >= 0 && gx < WW) {
                const float* p = inbase + (size_t)(gy * WW + gx) * pix_stride + cb;
#pragma unroll
                for (int ci = 0; ci < CCH; ci++) s_in[ci][yy][xx] = __ldg(&p[ci]);
            } else {
#pragma unroll
                for (int ci = 0; ci < CCH; ci++) s_in[ci][yy][xx] = 0.0f;
            }
        }
        // load weight chunk: w[(t*CIN + cb+ci)*COUT + co]
        for (int idx = tid; idx < 9 * CCH * COUT; idx += 256) {
            int co = idx % COUT;
            int rest = idx / COUT;
            int ci = rest % CCH;
            int t = rest / CCH;
            s_w[t][ci][co] = __ldg(&w[((size_t)t * CIN + cb + ci) * COUT + co]);
        }
        __syncthreads();

        for (int t = 0; t < 9; t++) {
            int dy = t / 3, dx = t % 3;
#pragma unroll
            for (int ci = 0; ci < CCH; ci++) {
                float v = s_in[ci][ty + dy][tx + dx];
                if (COUT % 4 == 0) {
#pragma unroll
                    for (int co = 0; co < COUT; co += 4) {
                        float4 wv = *(const float4*)&s_w[t][ci][co];
                        acc[co + 0] += v * wv.x;
                        acc[co + 1] += v * wv.y;
                        acc[co + 2] += v * wv.z;
                        acc[co + 3] += v * wv.w;
                    }
                } else {
#pragma unroll
                    for (int co = 0; co < COUT; co++) acc[co] += v * s_w[t][ci][co];
                }
            }
        }
    }

    const int gy = by * 16 + ty, gx = bx * 16 + tx;
    float* dst = out + ((size_t)layer * HH * WW + (size_t)gy * WW + gx) * out_stride + out_off;
#pragma unroll
    for (int c = 0; c < COUT; c++) {
        float v = acc[c] + __ldg(&bias[c]);
        if (RELU) v = fmaxf(v, 0.0f);
        dst[c] = v;
    }
}

// ============================================================================
// MPN conv2 (64->64) fused with sigmoid + cumprod-alpha compositing.
// in = g_hid [k][y][x][64]; fm = g_fm; out fuse [y][x][k].
// ============================================================================
__global__ __launch_bounds__(256) void mpn2_fuse_kernel(
    const float* __restrict__ in, const float* __restrict__ w,
    const float* __restrict__ bias, const float* __restrict__ fm,
    float* __restrict__ fuse) {
    constexpr int CIN = 64, CCH = 8, COUT = 64;
    __shared__ __align__(16) float s_in[CCH][18][18];
    __shared__ __align__(16) float s_w[9][CCH][COUT];

    const int tid = threadIdx.x;
    const int bx = blockIdx.x, by = blockIdx.y, layer = blockIdx.z;
    const int x0 = bx * 16 - 1, y0 = by * 16 - 1;
    const int tx = tid & 15, ty = tid >> 4;

    float acc[COUT];
#pragma unroll
    for (int c = 0; c < COUT; c++) acc[c] = 0.0f;

    const float* inbase = in + (size_t)layer * HH * WW * 64;

    for (int cb = 0; cb < CIN; cb += CCH) {
        __syncthreads();
        for (int idx = tid; idx < 18 * 18; idx += 256) {
            int yy = idx / 18, xx = idx % 18;
            int gy = y0 + yy, gx = x0 + xx;
            if (gy >= 0 && gy < HH && gx >= 0 && gx < WW) {
                const float* p = inbase + (size_t)(gy * WW + gx) * 64 + cb;
#pragma unroll
                for (int ci = 0; ci < CCH; ci++) s_in[ci][yy][xx] = __ldg(&p[ci]);
            } else {
#pragma unroll
                for (int ci = 0; ci < CCH; ci++) s_in[ci][yy][xx] = 0.0f;
            }
        }
        for (int idx = tid; idx < 9 * CCH * COUT; idx += 256) {
            int co = idx % COUT;
            int rest = idx / COUT;
            int ci = rest % CCH;
            int t = rest / CCH;
            s_w[t][ci][co] = __ldg(&w[((size_t)t * CIN + cb + ci) * COUT + co]);
        }
        __syncthreads();

        for (int t = 0; t < 9; t++) {
            int dy = t / 3, dx = t % 3;
#pragma unroll
            for (int ci = 0; ci < CCH; ci++) {
                float v = s_in[ci][ty + dy][tx + dx];
#pragma unroll
                for (int co = 0; co < COUT; co += 4) {
                    float4 wv = *(const float4*)&s_w[t][ci][co];
                    acc[co + 0] += v * wv.x;
                    acc[co + 1] += v * wv.y;
                    acc[co + 2] += v * wv.z;
                    acc[co + 3] += v * wv.w;
                }
            }
        }
    }

    const int gy = by * 16 + ty, gx = bx * 16 + tx;
    const float* fmp = fm + ((size_t)layer * HH * WW + (size_t)gy * WW + gx) * 64;
    float alpha = 1.0f, fu = 0.0f;
#pragma unroll
    for (int c = 0; c < 64; c++) {
        float mv = 1.0f / (1.0f + expf(-(acc[c] + __ldg(&bias[c]))));
        fu += __ldg(&fmp[c]) * mv * alpha;
        alpha *= (1.0f - mv);
    }
    fuse[((size_t)gy * WW + gx) * KK + layer] = fu;
}

// ============================================================================
// launch
// ============================================================================
extern "C" void kernel_launch(void* const* d_in, const int* in_sizes, int n_in,
                              void* d_out, int out_size) {
    const float* colors = (const float*)d_in[0];
    const float* ray = (const float*)d_in[1];
    const float* zbufs = (const float*)d_in[2];
    const float* W1 = (const float*)d_in[3];
    const float* b1 = (const float*)d_in[4];
    const float* W2 = (const float*)d_in[5];
    const float* b2 = (const float*)d_in[6];
    const float* W3 = (const float*)d_in[7];
    const float* b3 = (const float*)d_in[8];
    const float* W4 = (const float*)d_in[9];
    const float* b4 = (const float*)d_in[10];
    const float* k_sup1 = (const float*)d_in[11];
    const float* b_sup1 = (const float*)d_in[12];
    const float* k_sup2 = (const float*)d_in[13];
    const float* b_sup2 = (const float*)d_in[14];
    const float* k_mpn1 = (const float*)d_in[15];
    const float* b_mpn1 = (const float*)d_in[16];
    const float* k_mpn2 = (const float*)d_in[17];
    const float* b_mpn2 = (const float*)d_in[18];
    const float* k_un1 = (const float*)d_in[19];
    const float* b_un1 = (const float*)d_in[20];
    const float* k_un2 = (const float*)d_in[21];
    const float* b_un2 = (const float*)d_in[22];

    float *fm, *hid, *fuse, *un;
    cudaGetSymbolAddress((void**)&fm, g_fm);
    cudaGetSymbolAddress((void**)&hid, g_hid);
    cudaGetSymbolAddress((void**)&fuse, g_fuse);
    cudaGetSymbolAddress((void**)&un, g_un);

    const int npts = KK * HH * WW;
    mlp_kernel<<<npts / 64, 256>>>(ray, zbufs, W1, b1, W2, b2, W3, b3, W4, b4, fm);

    dim3 gk(WW / 16, HH / 16, KK);
    dim3 g1(WW / 16, HH / 16, 1);

    // sup1: colors (chmul=3 channel gather) -> hid (32ch layout), relu
    conv3x3_kernel<3, 3, 32, true><<<gk, 256>>>(colors, k_sup1, b_sup1, hid, 24,
                                                0LL, 3, 32, 0);
    // sup2: hid(32) -> fm[32:64]
    conv3x3_kernel<32, 16, 32, false><<<gk, 256>>>(
        hid, k_sup2, b_sup2, fm, 32, (long long)HH * WW * 32, 0, 64, 32);
    // mpn1: fm(64) -> hid(64), relu
    conv3x3_kernel<64, 8, 64, true><<<gk, 256>>>(
        fm, k_mpn1, b_mpn1, hid, 64, (long long)HH * WW * 64, 0, 64, 0);
    // mpn2 + sigmoid + compositing -> fuse [H,W,K]
    mpn2_fuse_kernel<<<gk, 256>>>(hid, k_mpn2, b_mpn2, fm, fuse);
    // un1: fuse(8) -> un(32), relu
    conv3x3_kernel<8, 8, 32, true><<<g1, 256>>>(fuse, k_un1, b_un1, un, 8, 0LL,
                                                0, 32, 0);
    // un2: un(32) -> out(3)
    conv3x3_kernel<32, 16, 3, false><<<g1, 256>>>(un, k_un2, b_un2,
                                                  (float*)d_out, 32, 0LL, 0, 3, 0);
}

// round 2
// speedup vs baseline: 1.0733x; 1.0733x over previous
#include <cuda_runtime.h>
#include <math.h>

#define HH 512
#define WW 512
#define KK 8

typedef unsigned long long u64;

// ---------------- packed f32x2 helpers --------------------------------------
__device__ __forceinline__ u64 pack2(float lo, float hi) {
    u64 r;
    asm("mov.b64 %0, {%1, %2};" : "=l"(r) : "f"(lo), "f"(hi));
    return r;
}
__device__ __forceinline__ void unpack2(u64 v, float& lo, float& hi) {
    asm("mov.b64 {%0, %1}, %2;" : "=f"(lo), "=f"(hi) : "l"(v));
}
__device__ __forceinline__ u64 ffma2(u64 a, u64 b, u64 c) {
    u64 d;
    asm("fma.rn.f32x2 %0, %1, %2, %3;" : "=l"(d) : "l"(a), "l"(b), "l"(c));
    return d;
}

// ---------------- scratch (static device globals; no runtime allocation) ----
__device__ float g_fm[(size_t)KK * HH * WW * 64];   // [k][y][x][64]: ch0-31=fz, ch32-63=fc
__device__ float g_hid[(size_t)KK * HH * WW * 64];  // reused: sup1 out (32ch), mpn1 out (64ch)
__device__ float g_fuse[(size_t)HH * WW * KK];      // [y][x][k]
__device__ float g_un[(size_t)HH * WW * 32];        // [y][x][32]

// ============================================================================
// MLP kernel: per-point 4-layer MLP -> g_fm channels 0..31 (masked)
// 64 points per block, 256 threads. Packed f32x2 accumulation.
// ============================================================================

__device__ __forceinline__ void gemm_64x128_p(const float (*As)[132],
                                              const float* __restrict__ Wt,
                                              int tx, int ty, u64 c2[4][4]) {
#pragma unroll
    for (int i = 0; i < 4; i++)
#pragma unroll
        for (int j = 0; j < 4; j++) c2[i][j] = 0ull;

    for (int kk = 0; kk < 128; kk += 4) {
        float4 a[4];
#pragma unroll
        for (int i = 0; i < 4; i++)
            a[i] = *(const float4*)&As[ty * 4 + i][kk];
        ulonglong2 b0[4], b1[4];
#pragma unroll
        for (int r = 0; r < 4; r++) {
            const float* wrow = Wt + (size_t)(kk + r) * 128 + tx * 8;
            b0[r] = __ldg((const ulonglong2*)wrow);
            b1[r] = __ldg((const ulonglong2*)(wrow + 4));
        }
#pragma unroll
        for (int i = 0; i < 4; i++) {
            float av[4] = {a[i].x, a[i].y, a[i].z, a[i].w};
#pragma unroll
            for (int r = 0; r < 4; r++) {
                u64 av2 = pack2(av[r], av[r]);
                c2[i][0] = ffma2(av2, b0[r].x, c2[i][0]);
                c2[i][1] = ffma2(av2, b0[r].y, c2[i][1]);
                c2[i][2] = ffma2(av2, b1[r].x, c2[i][2]);
                c2[i][3] = ffma2(av2, b1[r].y, c2[i][3]);
            }
        }
    }
}

__device__ __forceinline__ void unpack_c(const u64 c2[4][4], float c[4][8]) {
#pragma unroll
    for (int i = 0; i < 4; i++)
#pragma unroll
        for (int j = 0; j < 4; j++) unpack2(c2[i][j], c[i][2 * j], c[i][2 * j + 1]);
}

__global__ __launch_bounds__(256) void mlp_kernel(
    const float* __restrict__ ray, const float* __restrict__ zbufs,
    const float* __restrict__ W1, const float* __restrict__ b1,
    const float* __restrict__ W2, const float* __restrict__ b2,
    const float* __restrict__ W3, const float* __restrict__ b3,
    const float* __restrict__ W4, const float* __restrict__ b4,
    float* __restrict__ fm) {
    __shared__ __align__(16) float As[64][132];
    __shared__ float s_xyz[3][64];
    __shared__ float s_dirs[3][64];
    __shared__ float s_mask[64];

    const int tid = threadIdx.x;
    const size_t base = (size_t)blockIdx.x * 64;

    if (tid < 64) {
        size_t p = base + tid;
        int k = (int)(p / ((size_t)HH * WW));
        int rem = (int)(p % ((size_t)HH * WW));
        int y = rem / WW, x = rem % WW;
        const float* r = ray + (size_t)(y * WW + x) * 7;
        float z = zbufs[(size_t)(y * WW + x) * KK + k];
        float s = z / r[6];
        s_xyz[0][tid] = r[0] + r[3] * s;
        s_xyz[1][tid] = r[1] + r[4] * s;
        s_xyz[2][tid] = r[2] + r[5] * s;
        s_dirs[0][tid] = r[3];
        s_dirs[1][tid] = r[4];
        s_dirs[2][tid] = r[5];
        s_mask[tid] = (z > 0.0f) ? 1.0f : 0.0f;
    }
    __syncthreads();

    // ---- layer 1: h1 = relu(xyz @ W1 + b1) ----
    {
        int p = tid & 63;
        int jb = (tid >> 6) * 32;
        float x0 = s_xyz[0][p], x1 = s_xyz[1][p], x2 = s_xyz[2][p];
#pragma unroll
        for (int j = 0; j < 32; j++) {
            int jj = jb + j;
            float v = __ldg(&b1[jj]) + x0 * __ldg(&W1[jj]) + x1 * __ldg(&W1[128 + jj]) +
                      x2 * __ldg(&W1[256 + jj]);
            As[p][jj] = fmaxf(v, 0.0f);
        }
    }
    __syncthreads();

    const int tx = tid & 15;
    const int ty = tid >> 4;
    u64 c2[4][4];
    float c[4][8];

    // ---- layer 2: h2 = relu(h1 @ W2 + b2) ----
    gemm_64x128_p(As, W2, tx, ty, c2);
    unpack_c(c2, c);
    {
        float4 bb0 = __ldg((const float4*)&b2[tx * 8]);
        float4 bb1 = __ldg((const float4*)&b2[tx * 8 + 4]);
        __syncthreads();
#pragma unroll
        for (int i = 0; i < 4; i++) {
            int p = ty * 4 + i;
            float4 v0, v1;
            v0.x = fmaxf(c[i][0] + bb0.x, 0.0f);
            v0.y = fmaxf(c[i][1] + bb0.y, 0.0f);
            v0.z = fmaxf(c[i][2] + bb0.z, 0.0f);
            v0.w = fmaxf(c[i][3] + bb0.w, 0.0f);
            v1.x = fmaxf(c[i][4] + bb1.x, 0.0f);
            v1.y = fmaxf(c[i][5] + bb1.y, 0.0f);
            v1.z = fmaxf(c[i][6] + bb1.z, 0.0f);
            v1.w = fmaxf(c[i][7] + bb1.w, 0.0f);
            *(float4*)&As[p][tx * 8] = v0;
            *(float4*)&As[p][tx * 8 + 4] = v1;
        }
        __syncthreads();
    }

    // ---- layer 3: h3 = relu([h2, dirs] @ W3 + b3) ----
    gemm_64x128_p(As, W3, tx, ty, c2);
    unpack_c(c2, c);
    {
        float4 w30a = __ldg((const float4*)&W3[(size_t)128 * 128 + tx * 8]);
        float4 w30b = __ldg((const float4*)&W3[(size_t)128 * 128 + tx * 8 + 4]);
        float4 w31a = __ldg((const float4*)&W3[(size_t)129 * 128 + tx * 8]);
        float4 w31b = __ldg((const float4*)&W3[(size_t)129 * 128 + tx * 8 + 4]);
        float4 w32a = __ldg((const float4*)&W3[(size_t)130 * 128 + tx * 8]);
        float4 w32b = __ldg((const float4*)&W3[(size_t)130 * 128 + tx * 8 + 4]);
        float4 bb0 = __ldg((const float4*)&b3[tx * 8]);
        float4 bb1 = __ldg((const float4*)&b3[tx * 8 + 4]);
#pragma unroll
        for (int i = 0; i < 4; i++) {
            int p = ty * 4 + i;
            float d0 = s_dirs[0][p], d1 = s_dirs[1][p], d2 = s_dirs[2][p];
            c[i][0] += d0 * w30a.x + d1 * w31a.x + d2 * w32a.x;
            c[i][1] += d0 * w30a.y + d1 * w31a.y + d2 * w32a.y;
            c[i][2] += d0 * w30a.z + d1 * w31a.z + d2 * w32a.z;
            c[i][3] += d0 * w30a.w + d1 * w31a.w + d2 * w32a.w;
            c[i][4] += d0 * w30b.x + d1 * w31b.x + d2 * w32b.x;
            c[i][5] += d0 * w30b.y + d1 * w31b.y + d2 * w32b.y;
            c[i][6] += d0 * w30b.z + d1 * w31b.z + d2 * w32b.z;
            c[i][7] += d0 * w30b.w + d1 * w31b.w + d2 * w32b.w;
        }
        __syncthreads();
#pragma unroll
        for (int i = 0; i < 4; i++) {
            int p = ty * 4 + i;
            float4 v0, v1;
            v0.x = fmaxf(c[i][0] + bb0.x, 0.0f);
            v0.y = fmaxf(c[i][1] + bb0.y, 0.0f);
            v0.z = fmaxf(c[i][2] + bb0.z, 0.0f);
            v0.w = fmaxf(c[i][3] + bb0.w, 0.0f);
            v1.x = fmaxf(c[i][4] + bb1.x, 0.0f);
            v1.y = fmaxf(c[i][5] + bb1.y, 0.0f);
            v1.z = fmaxf(c[i][6] + bb1.z, 0.0f);
            v1.w = fmaxf(c[i][7] + bb1.w, 0.0f);
            *(float4*)&As[p][tx * 8] = v0;
            *(float4*)&As[p][tx * 8 + 4] = v1;
        }
        __syncthreads();
    }

    // ---- layer 4: feat = (h3 @ W4 + b4) * mask -> fm[:, 0:32] ----
    {
        int p = tid & 63;
        int jb = (tid >> 6) * 8;
        u64 acc2[4] = {0ull, 0ull, 0ull, 0ull};
        for (int kk = 0; kk < 128; kk += 4) {
            float4 a = *(const float4*)&As[p][kk];
            float av[4] = {a.x, a.y, a.z, a.w};
#pragma unroll
            for (int r = 0; r < 4; r++) {
                const float* wrow = W4 + (size_t)(kk + r) * 32 + jb;
                ulonglong2 w0 = __ldg((const ulonglong2*)wrow);
                ulonglong2 w1 = __ldg((const ulonglong2*)(wrow + 4));
                u64 av2 = pack2(av[r], av[r]);
                acc2[0] = ffma2(av2, w0.x, acc2[0]);
                acc2[1] = ffma2(av2, w0.y, acc2[1]);
                acc2[2] = ffma2(av2, w1.x, acc2[2]);
                acc2[3] = ffma2(av2, w1.y, acc2[3]);
            }
        }
        float acc[8];
#pragma unroll
        for (int j = 0; j < 4; j++) unpack2(acc2[j], acc[2 * j], acc[2 * j + 1]);
        float mk = s_mask[p];
        float4 bb0 = __ldg((const float4*)&b4[jb]);
        float4 bb1 = __ldg((const float4*)&b4[jb + 4]);
        float4 o0, o1;
        o0.x = (acc[0] + bb0.x) * mk;
        o0.y = (acc[1] + bb0.y) * mk;
        o0.z = (acc[2] + bb0.z) * mk;
        o0.w = (acc[3] + bb0.w) * mk;
        o1.x = (acc[4] + bb1.x) * mk;
        o1.y = (acc[5] + bb1.y) * mk;
        o1.z = (acc[6] + bb1.z) * mk;
        o1.w = (acc[7] + bb1.w) * mk;
        float* dst = fm + (base + p) * 64 + jb;
        *(float4*)dst = o0;
        *(float4*)(dst + 4) = o1;
    }
}

// ============================================================================
// Conv building blocks: staged loads + packed-FFMA inner product.
// ============================================================================
template <int CIN, int CCH, int COUT>
__device__ __forceinline__ void conv_stage_loads(
    float (*s_in)[18][18], float (*s_w)[CCH][COUT], const float* __restrict__ inbase,
    const float* __restrict__ w, int cb, int x0, int y0, int pix_stride, int tid) {
    constexpr bool VEC_IN = (CCH % 4 == 0);
    constexpr bool VEC_W = (COUT % 4 == 0);
    // input tile chunk
    for (int idx = tid; idx < 18 * 18; idx += 256) {
        int yy = idx / 18, xx = idx % 18;
        int gy = y0 + yy, gx = x0 + xx;
        if (gy >= 0 && gy < HH && gx >= 0 && gx < WW) {
            const float* p = inbase + (size_t)(gy * WW + gx) * pix_stride + cb;
            if (VEC_IN) {
#pragma unroll
                for (int c4 = 0; c4 < CCH / 4; c4++) {
                    float4 v = __ldg((const float4*)(p + 4 * c4));
                    s_in[4 * c4 + 0][yy][xx] = v.x;
                    s_in[4 * c4 + 1][yy][xx] = v.y;
                    s_in[4 * c4 + 2][yy][xx] = v.z;
                    s_in[4 * c4 + 3][yy][xx] = v.w;
                }
            } else {
#pragma unroll
                for (int ci = 0; ci < CCH; ci++) s_in[ci][yy][xx] = __ldg(&p[ci]);
            }
        } else {
#pragma unroll
            for (int ci = 0; ci < CCH; ci++) s_in[ci][yy][xx] = 0.0f;
        }
    }
    // weight chunk: per t, contiguous CCH*COUT block
    if (VEC_W) {
        constexpr int PER_T = CCH * COUT / 4;
        for (int idx = tid; idx < 9 * PER_T; idx += 256) {
            int t = idx / PER_T;
            int r = idx - t * PER_T;
            const float4* src = (const float4*)(w + ((size_t)t * CIN + cb) * COUT);
            ((float4*)&s_w[t][0][0])[r] = __ldg(&src[r]);
        }
    } else {
        for (int idx = tid; idx < 9 * CCH * COUT; idx += 256) {
            int co = idx % COUT;
            int rest = idx / COUT;
            int ci = rest % CCH;
            int t = rest / CCH;
            s_w[t][ci][co] = __ldg(&w[((size_t)t * CIN + cb + ci) * COUT + co]);
        }
    }
}

template <int CCH, int COUT>
__device__ __forceinline__ void conv_compute(const float (*s_in)[18][18],
                                             const float (*s_w)[CCH][COUT], int tx,
                                             int ty, u64* acc2, float* acc_s) {
#pragma unroll
    for (int t = 0; t < 9; t++) {
        const int dy = t / 3, dx = t % 3;
#pragma unroll
        for (int ci = 0; ci < CCH; ci++) {
            float v = s_in[ci][ty + dy][tx + dx];
            if (COUT % 4 == 0) {
                u64 v2 = pack2(v, v);
                const ulonglong2* wp = (const ulonglong2*)&s_w[t][ci][0];
#pragma unroll
                for (int q = 0; q < COUT / 4; q++) {
                    ulonglong2 wv = wp[q];
                    acc2[2 * q + 0] = ffma2(v2, wv.x, acc2[2 * q + 0]);
                    acc2[2 * q + 1] = ffma2(v2, wv.y, acc2[2 * q + 1]);
                }
            } else {
#pragma unroll
                for (int co = 0; co < COUT; co++) acc_s[co] += v * s_w[t][ci][co];
            }
        }
    }
}

// ============================================================================
// Generic direct 3x3 SAME conv, 16x16 output tile, cin-chunked, packed FFMA.
// ============================================================================
template <int CIN, int CCH, int COUT, bool RELU>
__global__ __launch_bounds__(256) void conv3x3_kernel(
    const float* __restrict__ in, const float* __restrict__ w,
    const float* __restrict__ bias, float* __restrict__ out, int pix_stride,
    long long layer_stride, int chmul, int out_stride, int out_off) {
    __shared__ __align__(16) float s_in[CCH][18][18];
    __shared__ __align__(16) float s_w[9][CCH][COUT];

    const int tid = threadIdx.x;
    const int bx = blockIdx.x, by = blockIdx.y, layer = blockIdx.z;
    const int x0 = bx * 16 - 1, y0 = by * 16 - 1;
    const int tx = tid & 15, ty = tid >> 4;

    u64 acc2[COUT % 4 == 0 ? COUT / 2 : 1];
    float acc_s[COUT % 4 == 0 ? 1 : COUT];
    if (COUT % 4 == 0) {
#pragma unroll
        for (int q = 0; q < COUT / 2; q++) acc2[q] = 0ull;
    } else {
#pragma unroll
        for (int c = 0; c < COUT; c++) acc_s[c] = 0.0f;
    }

    const float* inbase = in + (size_t)layer * (size_t)layer_stride + (size_t)layer * chmul;

    for (int cb = 0; cb < CIN; cb += CCH) {
        __syncthreads();
        conv_stage_loads<CIN, CCH, COUT>(s_in, s_w, inbase, w, cb, x0, y0, pix_stride, tid);
        __syncthreads();
        conv_compute<CCH, COUT>(s_in, s_w, tx, ty, acc2, acc_s);
    }

    const int gy = by * 16 + ty, gx = bx * 16 + tx;
    float* dst = out + ((size_t)layer * HH * WW + (size_t)gy * WW + gx) * out_stride + out_off;
    if (COUT % 4 == 0) {
#pragma unroll
        for (int q = 0; q < COUT / 2; q++) {
            float a0, a1;
            unpack2(acc2[q], a0, a1);
            float v0 = a0 + __ldg(&bias[2 * q]);
            float v1 = a1 + __ldg(&bias[2 * q + 1]);
            if (RELU) {
                v0 = fmaxf(v0, 0.0f);
                v1 = fmaxf(v1, 0.0f);
            }
            dst[2 * q] = v0;
            dst[2 * q + 1] = v1;
        }
    } else {
#pragma unroll
        for (int c = 0; c < COUT; c++) {
            float v = acc_s[c] + __ldg(&bias[c]);
            if (RELU) v = fmaxf(v, 0.0f);
            dst[c] = v;
        }
    }
}

// ============================================================================
// MPN conv2 (64->64) fused with sigmoid + cumprod-alpha compositing.
// ============================================================================
__global__ __launch_bounds__(256) void mpn2_fuse_kernel(
    const float* __restrict__ in, const float* __restrict__ w,
    const float* __restrict__ bias, const float* __restrict__ fm,
    float* __restrict__ fuse) {
    constexpr int CIN = 64, CCH = 8, COUT = 64;
    __shared__ __align__(16) float s_in[CCH][18][18];
    __shared__ __align__(16) float s_w[9][CCH][COUT];

    const int tid = threadIdx.x;
    const int bx = blockIdx.x, by = blockIdx.y, layer = blockIdx.z;
    const int x0 = bx * 16 - 1, y0 = by * 16 - 1;
    const int tx = tid & 15, ty = tid >> 4;

    u64 acc2[COUT / 2];
#pragma unroll
    for (int q = 0; q < COUT / 2; q++) acc2[q] = 0ull;

    const float* inbase = in + (size_t)layer * HH * WW * 64;

    for (int cb = 0; cb < CIN; cb += CCH) {
        __syncthreads();
        conv_stage_loads<CIN, CCH, COUT>(s_in, s_w, inbase, w, cb, x0, y0, 64, tid);
        __syncthreads();
        conv_compute<CCH, COUT>(s_in, s_w, tx, ty, acc2, (float*)nullptr);
    }

    const int gy = by * 16 + ty, gx = bx * 16 + tx;
    const float* fmp = fm + ((size_t)layer * HH * WW + (size_t)gy * WW + gx) * 64;
    float alpha = 1.0f, fu = 0.0f;
#pragma unroll
    for (int q = 0; q < 32; q++) {
        float a0, a1;
        unpack2(acc2[q], a0, a1);
        float m0 = 1.0f / (1.0f + __expf(-(a0 + __ldg(&bias[2 * q]))));
        fu += __ldg(&fmp[2 * q]) * m0 * alpha;
        alpha *= (1.0f - m0);
        float m1 = 1.0f / (1.0f + __expf(-(a1 + __ldg(&bias[2 * q + 1]))));
        fu += __ldg(&fmp[2 * q + 1]) * m1 * alpha;
        alpha *= (1.0f - m1);
    }
    fuse[((size_t)gy * WW + gx) * KK + layer] = fu;
}

// ============================================================================
// launch
// ============================================================================
extern "C" void kernel_launch(void* const* d_in, const int* in_sizes, int n_in,
                              void* d_out, int out_size) {
    const float* colors = (const float*)d_in[0];
    const float* ray = (const float*)d_in[1];
    const float* zbufs = (const float*)d_in[2];
    const float* W1 = (const float*)d_in[3];
    const float* b1 = (const float*)d_in[4];
    const float* W2 = (const float*)d_in[5];
    const float* b2 = (const float*)d_in[6];
    const float* W3 = (const float*)d_in[7];
    const float* b3 = (const float*)d_in[8];
    const float* W4 = (const float*)d_in[9];
    const float* b4 = (const float*)d_in[10];
    const float* k_sup1 = (const float*)d_in[11];
    const float* b_sup1 = (const float*)d_in[12];
    const float* k_sup2 = (const float*)d_in[13];
    const float* b_sup2 = (const float*)d_in[14];
    const float* k_mpn1 = (const float*)d_in[15];
    const float* b_mpn1 = (const float*)d_in[16];
    const float* k_mpn2 = (const float*)d_in[17];
    const float* b_mpn2 = (const float*)d_in[18];
    const float* k_un1 = (const float*)d_in[19];
    const float* b_un1 = (const float*)d_in[20];
    const float* k_un2 = (const float*)d_in[21];
    const float* b_un2 = (const float*)d_in[22];

    float *fm, *hid, *fuse, *un;
    cudaGetSymbolAddress((void**)&fm, g_fm);
    cudaGetSymbolAddress((void**)&hid, g_hid);
    cudaGetSymbolAddress((void**)&fuse, g_fuse);
    cudaGetSymbolAddress((void**)&un, g_un);

    const int npts = KK * HH * WW;
    mlp_kernel<<<npts / 64, 256>>>(ray, zbufs, W1, b1, W2, b2, W3, b3, W4, b4, fm);

    dim3 gk(WW / 16, HH / 16, KK);
    dim3 g1(WW / 16, HH / 16, 1);

    // sup1: colors (chmul=3 channel gather) -> hid (32ch layout), relu
    conv3x3_kernel<3, 3, 32, true><<<gk, 256>>>(colors, k_sup1, b_sup1, hid, 24,
                                                0LL, 3, 32, 0);
    // sup2: hid(32) -> fm[32:64]
    conv3x3_kernel<32, 16, 32, false><<<gk, 256>>>(
        hid, k_sup2, b_sup2, fm, 32, (long long)HH * WW * 32, 0, 64, 32);
    // mpn1: fm(64) -> hid(64), relu
    conv3x3_kernel<64, 8, 64, true><<<gk, 256>>>(
        fm, k_mpn1, b_mpn1, hid, 64, (long long)HH * WW * 64, 0, 64, 0);
    // mpn2 + sigmoid + compositing -> fuse [H,W,K]
    mpn2_fuse_kernel<<<gk, 256>>>(hid, k_mpn2, b_mpn2, fm, fuse);
    // un1: fuse(8) -> un(32), relu
    conv3x3_kernel<8, 8, 32, true><<<g1, 256>>>(fuse, k_un1, b_un1, un, 8, 0LL,
                                                0, 32, 0);
    // un2: un(32) -> out(3)
    conv3x3_kernel<32, 16, 3, false><<<g1, 256>>>(un, k_un2, b_un2,
                                                  (float*)d_out, 32, 0LL, 0, 3, 0);
}